// round 10
// baseline (speedup 1.0000x reference)
#include <cuda_runtime.h>
#include <cuda_fp16.h>
#include <cstdint>

#define HID      100
#define BATCH    512
#define TSTEPS   512
#define NCHUNK   8
#define CHUNKB   64
#define NSTAGES  10
#define NTHREADS 512
#define RING_D   4
#define NPAIRS   ((NSTAGES-1)*NCHUNK)   // 72

#define SCALE_LO 2048.0f
#define INV_LO   (1.0f/2048.0f)
#define APITCH   464                    // A row pitch (bytes): conflict-free ldmatrix phases

// ---- smem byte offsets ----
#define S_RED    0                       // 2048
#define S_BI_HI  2048                    // B input region  [64][128] f16 = 16KB
#define S_BI_LO  (S_BI_HI + 16384)
#define S_BH_HI  (S_BI_LO + 16384)       // B hidden region [64][128] f16
#define S_BH_LO  (S_BH_HI + 16384)
#define S_A_HI   (S_BH_LO + 16384)       // A [128 rows][224 k] f16, pitch 464B
#define S_A_LO   (S_A_HI + 128*APITCH)
#define SMEM_BYTES (S_A_LO + 128*APITCH) // 186368

#define RING_SLOT 32768
__device__ unsigned char g_ring[(size_t)NPAIRS * RING_D * RING_SLOT];
__device__ unsigned g_prod[NPAIRS];
__device__ unsigned g_cons[NPAIRS];

__device__ __forceinline__ uint32_t smem_u32(const void* p) {
    uint32_t a;
    asm("{ .reg .u64 t; cvta.to.shared.u64 t, %1; cvt.u32.u64 %0, t; }" : "=r"(a) : "l"(p));
    return a;
}
__device__ __forceinline__ unsigned ld_acq(const unsigned* p) {
    unsigned v;
    asm volatile("ld.acquire.gpu.global.u32 %0, [%1];" : "=r"(v) : "l"(p) : "memory");
    return v;
}
__device__ __forceinline__ void st_rel(unsigned* p, unsigned v) {
    asm volatile("st.release.gpu.global.u32 [%0], %1;" :: "l"(p), "r"(v) : "memory");
}

#define LDSM4(r0, r1, r2, r3, addr) \
    asm volatile("ldmatrix.sync.aligned.m8n8.x4.shared.b16 {%0,%1,%2,%3}, [%4];" \
        : "=r"(r0), "=r"(r1), "=r"(r2), "=r"(r3) : "r"(addr))

#define MMA(d, a0_, a1_, a2_, a3_, b0_, b1_) \
    asm volatile("mma.sync.aligned.m16n8k16.row.col.f32.f16.f16.f32 " \
        "{%0,%1,%2,%3}, {%4,%5,%6,%7}, {%8,%9}, {%0,%1,%2,%3};" \
        : "+f"((d)[0]), "+f"((d)[1]), "+f"((d)[2]), "+f"((d)[3]) \
        : "r"(a0_), "r"(a1_), "r"(a2_), "r"(a3_), "r"(b0_), "r"(b1_))

__device__ __forceinline__ void split16(float v, __half& hi, __half& lo) {
    hi = __float2half_rn(v);
    lo = __float2half_rn((v - __half2float(hi)) * SCALE_LO);
}
__device__ __forceinline__ float fast_tanh(float x) {
    float e, r;
    asm("ex2.approx.f32 %0, %1;" : "=f"(e) : "f"(x * 2.8853900817779268f)); // 2*log2(e)
    asm("rcp.approx.f32 %0, %1;" : "=f"(r) : "f"(e + 1.0f));
    return fmaf(-2.0f, r, 1.0f);
}
// B buffers: [n 64][k 128] f16, row 256B, 16B-unit swizzle by (n&7)
__device__ __forceinline__ uint32_t b_off(int n, int kbyte) {
    return (uint32_t)n * 256u + ((uint32_t)kbyte ^ (((uint32_t)n & 7u) << 4));
}

__global__ void rnn_reset_kernel() {
    int i = threadIdx.x;
    if (i < NPAIRS) { g_prod[i] = 0u; g_cons[i] = 0u; }
}

__global__ __launch_bounds__(NTHREADS, 1)
void rnn_mma_kernel(const float* __restrict__ x,    const float* __restrict__ h0,
                    const float* __restrict__ Wi0,  const float* __restrict__ Wih,
                    const float* __restrict__ Whh,  const float* __restrict__ bih,
                    const float* __restrict__ bhh,  const float* __restrict__ Wout,
                    const float* __restrict__ bout, float* __restrict__ out)
{
    extern __shared__ __align__(128) unsigned char sm[];
    const uint32_t smb = smem_u32(sm);
    const int tid = threadIdx.x, warp = tid >> 5, lane = tid & 31;
    const int stage = blockIdx.x >> 3, chunk = blockIdx.x & 7;
    const int b0 = chunk * CHUNKB, l = stage;
    const bool first = (stage == 0), last = (stage == NSTAGES - 1);
    const bool mwarp = (warp < 14);
    const int wm = warp % 7, wn = warp / 7;   // m-tile, n-half (wn in {0,1}; warps 14,15 idle)

    // ---- zero all smem ----
    for (int i = tid; i < SMEM_BYTES / 16; i += NTHREADS)
        ((float4*)sm)[i] = make_float4(0.f, 0.f, 0.f, 0.f);
    __syncthreads();

    // ---- A fill: [m 128][k 224] f16, pitch 464B. I=k[0,112), H=k[112,224) ----
    if (first) {
        for (int idx = tid; idx < HID * HID; idx += NTHREADS) {
            int jj = idx / HID, kk = idx % HID;
            __half hi, lo; split16(Whh[idx], hi, lo);
            uint32_t o = (uint32_t)jj * APITCH + 2u * (112 + kk);
            *(__half*)(sm + S_A_HI + o) = hi; *(__half*)(sm + S_A_LO + o) = lo;
        }
        for (int jj = tid; jj < HID; jj += NTHREADS) {
            __half hi, lo; split16(Wi0[jj], hi, lo);
            uint32_t o = (uint32_t)jj * APITCH;              // x at k=0
            *(__half*)(sm + S_A_HI + o) = hi; *(__half*)(sm + S_A_LO + o) = lo;
        }
    } else {
        for (int idx = tid; idx < 2 * HID * HID; idx += NTHREADS) {
            int m = idx / (HID * HID), r = idx % (HID * HID);
            int jj = r / HID, kk = r % HID;
            float v = m ? Whh[(size_t)l * HID * HID + r] : Wih[(size_t)(l - 1) * HID * HID + r];
            __half hi, lo; split16(v, hi, lo);
            uint32_t o = (uint32_t)jj * APITCH + 2u * (m ? 112 + kk : kk);
            *(__half*)(sm + S_A_HI + o) = hi; *(__half*)(sm + S_A_LO + o) = lo;
        }
    }
    // ---- BH fill from h0 ----
    for (int idx = tid; idx < CHUNKB * HID; idx += NTHREADS) {
        int b = idx / HID, jj = idx % HID;
        __half hi, lo; split16(h0[((size_t)l * BATCH + b0 + b) * HID + jj], hi, lo);
        uint32_t o = b_off(b, 2 * jj);
        *(__half*)(sm + S_BH_HI + o) = hi;
        *(__half*)(sm + S_BH_LO + o) = lo;
    }
    __syncthreads();

    // ---- A-hi fragments -> registers (14 MMA warps); A-lo streamed per step ----
    const uint32_t aRow = 16u * (uint32_t)wm + (uint32_t)(lane & 15);
    const uint32_t aCol = ((uint32_t)(lane >> 4)) << 4;
    const uint32_t aHiBase = smb + S_A_HI + aRow * APITCH + aCol;
    const uint32_t aLoBase = smb + S_A_LO + aRow * APITCH + aCol;
    uint32_t AH[14][4];
    if (mwarp) {
#pragma unroll
        for (int ci = 0; ci < 14; ci++)
            LDSM4(AH[ci][0], AH[ci][1], AH[ci][2], AH[ci][3], aHiBase + 32u * ci);
    }

    const int j0 = 16 * wm + (lane >> 2), j1 = j0 + 8;
    float bias0 = 0.f, bias1 = 0.f, w0 = 0.f, w1 = 0.f;
    if (mwarp) {
        if (j0 < HID) bias0 = bih[l * HID + j0] + bhh[l * HID + j0];
        if (j1 < HID) bias1 = bih[l * HID + j1] + bhh[l * HID + j1];
        if (last) {
            if (j0 < HID) w0 = Wout[j0];
            if (j1 < HID) w1 = Wout[j1];
        }
    }
    const float boutv = bout[0];

    const int pc_in = (stage - 1) * NCHUNK + chunk, pc_out = stage * NCHUNK + chunk;
    unsigned char* ring_in  = g_ring + (size_t)pc_in  * RING_D * RING_SLOT;
    unsigned char* ring_out = g_ring + (size_t)pc_out * RING_D * RING_SLOT;

    float xv = 0.f;
    if (first && tid < CHUNKB) xv = x[(size_t)(b0 + tid) * TSTEPS];

    const uint32_t browoff = (uint32_t)(lane & 15) * 256u;
    const uint32_t bcol16  = ((uint32_t)(lane >> 4)) << 4;
    const uint32_t bswz    = ((uint32_t)(lane & 7)) << 4;
    const uint32_t pbase   = ((uint32_t)(2 * wn)) << 12;   // n-half byte offset (p = 2*wn)
    float* sRed = (float*)(sm + S_RED);

    // epilogue store offsets (constant per thread): nt adds nt*2048
    const int ec0 = 2 * (lane & 3), ec1 = ec0 + 1;
    const int cb = 32 * wn;   // column base of this warp's n-half
    const uint32_t o00 = b_off(cb + ec0, 2 * j0), o01 = b_off(cb + ec1, 2 * j0);
    const uint32_t o10 = b_off(cb + ec0, 2 * j1), o11 = b_off(cb + ec1, 2 * j1);

    for (int t = 0; t < TSTEPS; t++) {
        // -------- phase 0: poll + prefetch ring into regs (stage>0) --------
        float4 pf[4];
        if (first) {
            if (tid < CHUNKB) {
                __half hi, lo; split16(xv, hi, lo);
                uint32_t o = b_off(tid, 0);
                *(__half*)(sm + S_BI_HI + o) = hi;
                *(__half*)(sm + S_BI_LO + o) = lo;
                if (t + 1 < TSTEPS) xv = x[(size_t)(b0 + tid) * TSTEPS + t + 1];
            }
        } else {
            while (ld_acq(&g_prod[pc_in]) < (unsigned)(t + 1)) {}
            const float4* src = (const float4*)(ring_in + (size_t)(t & (RING_D - 1)) * RING_SLOT);
#pragma unroll
            for (int i = 0; i < 4; i++) pf[i] = __ldcg(src + tid + i * NTHREADS);
        }

        // -------- phase 1: hidden-part MMA (ci 7..13) --------
        float acc1[4][4], acc2[4][4];
        if (mwarp) {
#pragma unroll
            for (int nt = 0; nt < 4; nt++) {
                acc1[nt][0] = bias0; acc1[nt][1] = bias0;
                acc1[nt][2] = bias1; acc1[nt][3] = bias1;
                acc2[nt][0] = 0.f; acc2[nt][1] = 0.f; acc2[nt][2] = 0.f; acc2[nt][3] = 0.f;
            }
#pragma unroll
            for (int ci = 7; ci < 14; ci++) {
                uint32_t AL0, AL1, AL2, AL3;
                LDSM4(AL0, AL1, AL2, AL3, aLoBase + 32u * ci);
                uint32_t colx = ((32u * (uint32_t)(ci - 7)) + bcol16) ^ bswz;
#pragma unroll
                for (int q = 0; q < 2; q++) {
                    uint32_t ab = smb + S_BH_HI + pbase + ((uint32_t)q << 12) + browoff + colx;
                    uint32_t bh0, bh1, bh2, bh3, bl0, bl1, bl2, bl3;
                    LDSM4(bh0, bh1, bh2, bh3, ab);
                    LDSM4(bl0, bl1, bl2, bl3, ab + 16384u);
                    MMA(acc1[2 * q],     AH[ci][0], AH[ci][1], AH[ci][2], AH[ci][3], bh0, bh2);
                    MMA(acc1[2 * q + 1], AH[ci][0], AH[ci][1], AH[ci][2], AH[ci][3], bh1, bh3);
                    MMA(acc2[2 * q],     AH[ci][0], AH[ci][1], AH[ci][2], AH[ci][3], bl0, bl2);
                    MMA(acc2[2 * q + 1], AH[ci][0], AH[ci][1], AH[ci][2], AH[ci][3], bl1, bl3);
                    MMA(acc2[2 * q],     AL0, AL1, AL2, AL3, bh0, bh2);
                    MMA(acc2[2 * q + 1], AL0, AL1, AL2, AL3, bh1, bh3);
                }
            }
        }

        // -------- phase 2: stage input, sync --------
        if (!first) {
            float4* dst = (float4*)(sm + S_BI_HI);
#pragma unroll
            for (int i = 0; i < 4; i++) dst[tid + i * NTHREADS] = pf[i];
        }
        __syncthreads();   // input staged; all BH reads (phase 1) complete
        if (!first && tid == 0) st_rel(&g_cons[pc_in], (unsigned)(t + 1));

        // -------- phase 3: input-part MMA (ci 0..6; stage0: ci 0 only) --------
        if (mwarp) {
#pragma unroll
            for (int ci = 0; ci < 7; ci++) {
                if (first && ci >= 1) break;
                uint32_t AL0, AL1, AL2, AL3;
                LDSM4(AL0, AL1, AL2, AL3, aLoBase + 32u * ci);
                uint32_t colx = ((32u * (uint32_t)ci) + bcol16) ^ bswz;
#pragma unroll
                for (int q = 0; q < 2; q++) {
                    uint32_t ab = smb + S_BI_HI + pbase + ((uint32_t)q << 12) + browoff + colx;
                    uint32_t bh0, bh1, bh2, bh3, bl0, bl1, bl2, bl3;
                    LDSM4(bh0, bh1, bh2, bh3, ab);
                    LDSM4(bl0, bl1, bl2, bl3, ab + 16384u);
                    MMA(acc1[2 * q],     AH[ci][0], AH[ci][1], AH[ci][2], AH[ci][3], bh0, bh2);
                    MMA(acc1[2 * q + 1], AH[ci][0], AH[ci][1], AH[ci][2], AH[ci][3], bh1, bh3);
                    MMA(acc2[2 * q],     AH[ci][0], AH[ci][1], AH[ci][2], AH[ci][3], bl0, bl2);
                    MMA(acc2[2 * q + 1], AH[ci][0], AH[ci][1], AH[ci][2], AH[ci][3], bl1, bl3);
                    MMA(acc2[2 * q],     AL0, AL1, AL2, AL3, bh0, bh2);
                    MMA(acc2[2 * q + 1], AL0, AL1, AL2, AL3, bh1, bh3);
                }
            }

            // -------- phase 4: epilogue --------
#pragma unroll
            for (int nt = 0; nt < 4; nt++) {
                const uint32_t ntoff = (uint32_t)nt << 11;
                float h00 = fast_tanh(fmaf(acc2[nt][0], INV_LO, acc1[nt][0]));
                float h01 = fast_tanh(fmaf(acc2[nt][1], INV_LO, acc1[nt][1]));
                float h10 = fast_tanh(fmaf(acc2[nt][2], INV_LO, acc1[nt][2]));
                float h11 = fast_tanh(fmaf(acc2[nt][3], INV_LO, acc1[nt][3]));
                __half hi, lo;
                split16(h00, hi, lo);
                *(__half*)(sm + S_BH_HI + o00 + ntoff) = hi; *(__half*)(sm + S_BH_LO + o00 + ntoff) = lo;
                split16(h01, hi, lo);
                *(__half*)(sm + S_BH_HI + o01 + ntoff) = hi; *(__half*)(sm + S_BH_LO + o01 + ntoff) = lo;
                split16(h10, hi, lo);
                *(__half*)(sm + S_BH_HI + o10 + ntoff) = hi; *(__half*)(sm + S_BH_LO + o10 + ntoff) = lo;
                split16(h11, hi, lo);
                *(__half*)(sm + S_BH_HI + o11 + ntoff) = hi; *(__half*)(sm + S_BH_LO + o11 + ntoff) = lo;
                if (last) {
                    float p0 = h00 * w0 + h10 * w1;
                    float p1 = h01 * w0 + h11 * w1;
#pragma unroll
                    for (int d = 4; d < 32; d <<= 1) {
                        p0 += __shfl_xor_sync(0xFFFFFFFFu, p0, d);
                        p1 += __shfl_xor_sync(0xFFFFFFFFu, p1, d);
                    }
                    if (lane < 4) {
                        sRed[wm * 64 + cb + nt * 8 + ec0] = p0;
                        sRed[wm * 64 + cb + nt * 8 + ec1] = p1;
                    }
                }
            }
        }
        // backpressure poll before copy-out
        if (!last && t >= RING_D)
            while (ld_acq(&g_cons[pc_out]) < (unsigned)(t + 1 - RING_D)) {}
        __syncthreads();   // BH (and sRed) writes complete

        if (!last) {
            float4* dst = (float4*)(ring_out + (size_t)(t & (RING_D - 1)) * RING_SLOT);
            const float4* src = (const float4*)(sm + S_BH_HI);
#pragma unroll
            for (int i = 0; i < 4; i++) dst[tid + i * NTHREADS] = src[tid + i * NTHREADS];
            __syncthreads();
            if (tid == 0) st_rel(&g_prod[pc_out], (unsigned)(t + 1));
        } else {
            if (tid < CHUNKB) {
                float s = boutv;
#pragma unroll
                for (int w = 0; w < 7; w++) s += sRed[w * 64 + tid];
                out[(size_t)(b0 + tid) * TSTEPS + t] = s;
            }
            __syncthreads();
        }
    }

    // ---- final hidden state ----
    for (int idx = tid; idx < CHUNKB * HID; idx += NTHREADS) {
        int b = idx / HID, jj = idx % HID;
        uint32_t o = b_off(b, 2 * jj);
        float v = __half2float(*(const __half*)(sm + S_BH_HI + o))
                + __half2float(*(const __half*)(sm + S_BH_LO + o)) * INV_LO;
        out[(size_t)BATCH * TSTEPS + ((size_t)l * BATCH + b0 + b) * HID + jj] = v;
    }
}

extern "C" void kernel_launch(void* const* d_in, const int* in_sizes, int n_in,
                              void* d_out, int out_size) {
    const float* x    = (const float*)d_in[0];
    const float* h0   = (const float*)d_in[1];
    const float* Wi0  = (const float*)d_in[2];
    const float* Wih  = (const float*)d_in[3];
    const float* Whh  = (const float*)d_in[4];
    const float* bih  = (const float*)d_in[5];
    const float* bhh  = (const float*)d_in[6];
    const float* Wout = (const float*)d_in[7];
    const float* bout = (const float*)d_in[8];
    float* out = (float*)d_out;

    cudaFuncSetAttribute(rnn_mma_kernel, cudaFuncAttributeMaxDynamicSharedMemorySize, SMEM_BYTES);
    rnn_reset_kernel<<<1, 256>>>();
    rnn_mma_kernel<<<NSTAGES * NCHUNK, NTHREADS, SMEM_BYTES>>>(
        x, h0, Wi0, Wih, Whh, bih, bhh, Wout, bout, out);
}

// round 11
// speedup vs baseline: 1.3040x; 1.3040x over previous
#include <cuda_runtime.h>
#include <cuda_fp16.h>
#include <cstdint>

#define HID      100
#define BATCH    512
#define TSTEPS   512
#define NCHUNK   8
#define CHUNKB   64
#define NSTAGES  10
#define NTHREADS 256
#define RING_D   4
#define NPAIRS   ((NSTAGES-1)*NCHUNK)   // 72

#define SCALE_LO 2048.0f
#define INV_LO   (1.0f/2048.0f)
#define APITCH   464     // A row pitch (bytes): conflict-free ldmatrix phases
#define BPITCH   144     // B row pitch (bytes): [k][n] f16, conflict-free trans-ldmatrix + half2 stores

// ---- smem byte offsets ----
#define S_RED    0                        // 2048
#define S_BI_HI  2048                     // B input region  [112 k][64 n] f16, pitch 144 (16KB slot)
#define S_BI_LO  (S_BI_HI + 16384)
#define S_BH_HI  (S_BI_LO + 16384)        // B hidden region
#define S_BH_LO  (S_BH_HI + 16384)
#define S_A_HI   (S_BH_LO + 16384)        // A [128 m][224 k] f16, pitch 464B
#define S_A_LO   (S_A_HI + 128*APITCH)
#define SMEM_BYTES (S_A_LO + 128*APITCH)  // 186368

#define RING_SLOT 32768
__device__ unsigned char g_ring[(size_t)NPAIRS * RING_D * RING_SLOT];
__device__ unsigned g_prod[NPAIRS];
__device__ unsigned g_cons[NPAIRS];

__device__ __forceinline__ uint32_t smem_u32(const void* p) {
    uint32_t a;
    asm("{ .reg .u64 t; cvta.to.shared.u64 t, %1; cvt.u32.u64 %0, t; }" : "=r"(a) : "l"(p));
    return a;
}
__device__ __forceinline__ unsigned ld_acq(const unsigned* p) {
    unsigned v;
    asm volatile("ld.acquire.gpu.global.u32 %0, [%1];" : "=r"(v) : "l"(p) : "memory");
    return v;
}
__device__ __forceinline__ void st_rel(unsigned* p, unsigned v) {
    asm volatile("st.release.gpu.global.u32 [%0], %1;" :: "l"(p), "r"(v) : "memory");
}

#define LDSM4(r0, r1, r2, r3, addr) \
    asm volatile("ldmatrix.sync.aligned.m8n8.x4.shared.b16 {%0,%1,%2,%3}, [%4];" \
        : "=r"(r0), "=r"(r1), "=r"(r2), "=r"(r3) : "r"(addr))
#define LDSM4T(r0, r1, r2, r3, addr) \
    asm volatile("ldmatrix.sync.aligned.m8n8.x4.trans.shared.b16 {%0,%1,%2,%3}, [%4];" \
        : "=r"(r0), "=r"(r1), "=r"(r2), "=r"(r3) : "r"(addr))

#define MMA(d, a0_, a1_, a2_, a3_, b0_, b1_) \
    asm volatile("mma.sync.aligned.m16n8k16.row.col.f32.f16.f16.f32 " \
        "{%0,%1,%2,%3}, {%4,%5,%6,%7}, {%8,%9}, {%0,%1,%2,%3};" \
        : "+f"((d)[0]), "+f"((d)[1]), "+f"((d)[2]), "+f"((d)[3]) \
        : "r"(a0_), "r"(a1_), "r"(a2_), "r"(a3_), "r"(b0_), "r"(b1_))

__device__ __forceinline__ void split16(float v, __half& hi, __half& lo) {
    hi = __float2half_rn(v);
    lo = __float2half_rn((v - __half2float(hi)) * SCALE_LO);
}
__device__ __forceinline__ float fast_tanh(float x) {
    float e, r;
    asm("ex2.approx.f32 %0, %1;" : "=f"(e) : "f"(x * 2.8853900817779268f)); // 2*log2(e)
    asm("rcp.approx.f32 %0, %1;" : "=f"(r) : "f"(e + 1.0f));
    return fmaf(-2.0f, r, 1.0f);
}
// B regions: [k 112][n 64] f16, pitch BPITCH
__device__ __forceinline__ uint32_t b_off(int k, int n) {
    return (uint32_t)k * BPITCH + 2u * (uint32_t)n;
}

__global__ void rnn_reset_kernel() {
    int i = threadIdx.x;
    if (i < NPAIRS) { g_prod[i] = 0u; g_cons[i] = 0u; }
}

__global__ __launch_bounds__(NTHREADS, 1)
void rnn_mma_kernel(const float* __restrict__ x,    const float* __restrict__ h0,
                    const float* __restrict__ Wi0,  const float* __restrict__ Wih,
                    const float* __restrict__ Whh,  const float* __restrict__ bih,
                    const float* __restrict__ bhh,  const float* __restrict__ Wout,
                    const float* __restrict__ bout, float* __restrict__ out)
{
    extern __shared__ __align__(128) unsigned char sm[];
    const uint32_t smb = smem_u32(sm);
    const int tid = threadIdx.x, warp = tid >> 5, lane = tid & 31;
    const int stage = blockIdx.x >> 3, chunk = blockIdx.x & 7;
    const int b0 = chunk * CHUNKB, l = stage;
    const bool first = (stage == 0), last = (stage == NSTAGES - 1);
    const bool mwarp = (warp < 7);

    // ---- zero all smem ----
    for (int i = tid; i < SMEM_BYTES / 16; i += NTHREADS)
        ((float4*)sm)[i] = make_float4(0.f, 0.f, 0.f, 0.f);
    __syncthreads();

    // ---- A fill: [m 128][k 224] f16, pitch 464B. I=k[0,112), H=k[112,224) ----
    if (first) {
        for (int idx = tid; idx < HID * HID; idx += NTHREADS) {
            int jj = idx / HID, kk = idx % HID;
            __half hi, lo; split16(Whh[idx], hi, lo);
            uint32_t o = (uint32_t)jj * APITCH + 2u * (112 + kk);
            *(__half*)(sm + S_A_HI + o) = hi; *(__half*)(sm + S_A_LO + o) = lo;
        }
        for (int jj = tid; jj < HID; jj += NTHREADS) {
            __half hi, lo; split16(Wi0[jj], hi, lo);
            uint32_t o = (uint32_t)jj * APITCH;              // x weight at k=0
            *(__half*)(sm + S_A_HI + o) = hi; *(__half*)(sm + S_A_LO + o) = lo;
        }
    } else {
        for (int idx = tid; idx < 2 * HID * HID; idx += NTHREADS) {
            int m = idx / (HID * HID), r = idx % (HID * HID);
            int jj = r / HID, kk = r % HID;
            float v = m ? Whh[(size_t)l * HID * HID + r] : Wih[(size_t)(l - 1) * HID * HID + r];
            __half hi, lo; split16(v, hi, lo);
            uint32_t o = (uint32_t)jj * APITCH + 2u * (m ? 112 + kk : kk);
            *(__half*)(sm + S_A_HI + o) = hi; *(__half*)(sm + S_A_LO + o) = lo;
        }
    }
    // ---- BH fill from h0: row k=jj, col n=b ----
    for (int idx = tid; idx < CHUNKB * HID; idx += NTHREADS) {
        int b = idx & 63, jj = idx >> 6;
        __half hi, lo; split16(h0[((size_t)l * BATCH + b0 + b) * HID + jj], hi, lo);
        uint32_t o = b_off(jj, b);
        *(__half*)(sm + S_BH_HI + o) = hi;
        *(__half*)(sm + S_BH_LO + o) = lo;
    }
    __syncthreads();

    const int wm = warp;                       // m-tile for MMA warps 0..6
    const uint32_t aRow = 16u * (uint32_t)wm + (uint32_t)(lane & 15);
    const uint32_t aCol = ((uint32_t)(lane >> 4)) << 4;
    const uint32_t aHiBase = smb + S_A_HI + aRow * APITCH + aCol;
    const uint32_t aLoBase = smb + S_A_LO + aRow * APITCH + aCol;

    // B trans-ldmatrix lane address part: row = (lane&7) + ((lane>>3)&1)*8, col block = (lane>>4)*8
    const uint32_t brp = ((uint32_t)((lane & 7) + ((lane >> 3) & 1) * 8)) * BPITCH
                       + 16u * (uint32_t)(lane >> 4);

    const int j0 = 16 * wm + (lane >> 2), j1 = j0 + 8;
    float bias0 = 0.f, bias1 = 0.f, w0 = 0.f, w1 = 0.f;
    if (mwarp) {
        if (j0 < HID) bias0 = bih[l * HID + j0] + bhh[l * HID + j0];
        if (j1 < HID) bias1 = bih[l * HID + j1] + bhh[l * HID + j1];
        if (last) {
            if (j0 < HID) w0 = Wout[j0];
            if (j1 < HID) w1 = Wout[j1];
        }
    }
    const float boutv = bout[0];

    const int pc_in = (stage - 1) * NCHUNK + chunk, pc_out = stage * NCHUNK + chunk;
    unsigned char* ring_in  = g_ring + (size_t)pc_in  * RING_D * RING_SLOT;
    unsigned char* ring_out = g_ring + (size_t)pc_out * RING_D * RING_SLOT;

    float xv = 0.f;
    if (first && tid < CHUNKB) xv = x[(size_t)(b0 + tid) * TSTEPS];

    float* sRed = (float*)(sm + S_RED);
    // epilogue store column part: 2*(2*(lane&3)) = 4*(lane&3); nt adds 16*nt
    const uint32_t tcol = 4u * (uint32_t)(lane & 3);
    const uint32_t oj0 = (uint32_t)j0 * BPITCH + tcol;
    const uint32_t oj1 = (uint32_t)j1 * BPITCH + tcol;

    for (int t = 0; t < TSTEPS; t++) {
        // -------- phase 0: poll + prefetch ring into regs (stage>0) --------
        float4 pf[8];
        if (first) {
            if (tid < CHUNKB) {
                __half hi, lo; split16(xv, hi, lo);
                *(__half*)(sm + S_BI_HI + 2u * tid) = hi;   // row k=0
                *(__half*)(sm + S_BI_LO + 2u * tid) = lo;
                if (t + 1 < TSTEPS) xv = x[(size_t)(b0 + tid) * TSTEPS + t + 1];
            }
        } else {
            while (ld_acq(&g_prod[pc_in]) < (unsigned)(t + 1)) {}
            const float4* src = (const float4*)(ring_in + (size_t)(t & (RING_D - 1)) * RING_SLOT);
#pragma unroll
            for (int i = 0; i < 8; i++) pf[i] = __ldcg(src + tid + i * NTHREADS);
        }

        // -------- phase 1: hidden-part MMA (ci 7..13) --------
        float acc1[8][4], acc2a[8][4], acc2b[8][4];
        if (mwarp) {
#pragma unroll
            for (int nt = 0; nt < 8; nt++) {
                acc1[nt][0] = bias0; acc1[nt][1] = bias0;
                acc1[nt][2] = bias1; acc1[nt][3] = bias1;
#pragma unroll
                for (int r = 0; r < 4; r++) { acc2a[nt][r] = 0.f; acc2b[nt][r] = 0.f; }
            }
#pragma unroll
            for (int ci = 0; ci < 7; ci++) {
                uint32_t AH0, AH1, AH2, AH3, AL0, AL1, AL2, AL3;
                LDSM4(AH0, AH1, AH2, AH3, aHiBase + 32u * (ci + 7));
                LDSM4(AL0, AL1, AL2, AL3, aLoBase + 32u * (ci + 7));
                uint32_t bb = smb + S_BH_HI + (uint32_t)ci * (16u * BPITCH) + brp;
#pragma unroll
                for (int g = 0; g < 4; g++) {         // n-block groups: nb = 32*g/2... nb=16g
                    uint32_t ab = bb + 32u * g;       // 2*nb, nb = 16g
                    uint32_t h0r, h1r, h2r, h3r, l0r, l1r, l2r, l3r;
                    LDSM4T(h0r, h1r, h2r, h3r, ab);
                    LDSM4T(l0r, l1r, l2r, l3r, ab + 16384u);
                    MMA(acc1[2 * g],      AH0, AH1, AH2, AH3, h0r, h1r);
                    MMA(acc1[2 * g + 1],  AH0, AH1, AH2, AH3, h2r, h3r);
                    MMA(acc2a[2 * g],     AH0, AH1, AH2, AH3, l0r, l1r);
                    MMA(acc2a[2 * g + 1], AH0, AH1, AH2, AH3, l2r, l3r);
                    MMA(acc2b[2 * g],     AL0, AL1, AL2, AL3, h0r, h1r);
                    MMA(acc2b[2 * g + 1], AL0, AL1, AL2, AL3, h2r, h3r);
                }
            }
        }

        // -------- phase 2: stage input, sync --------
        if (!first) {
            float4* dst = (float4*)(sm + S_BI_HI);
#pragma unroll
            for (int i = 0; i < 8; i++) dst[tid + i * NTHREADS] = pf[i];
        }
        __syncthreads();   // input staged; all BH reads (phase 1) complete
        if (!first && tid == 0) st_rel(&g_cons[pc_in], (unsigned)(t + 1));

        // -------- phase 3: input-part MMA (ci 0..6; stage0: ci 0 only) --------
        if (mwarp) {
#pragma unroll
            for (int ci = 0; ci < 7; ci++) {
                if (first && ci >= 1) break;
                uint32_t AH0, AH1, AH2, AH3, AL0, AL1, AL2, AL3;
                LDSM4(AH0, AH1, AH2, AH3, aHiBase + 32u * ci);
                LDSM4(AL0, AL1, AL2, AL3, aLoBase + 32u * ci);
                uint32_t bb = smb + S_BI_HI + (uint32_t)ci * (16u * BPITCH) + brp;
#pragma unroll
                for (int g = 0; g < 4; g++) {
                    uint32_t ab = bb + 32u * g;
                    uint32_t h0r, h1r, h2r, h3r, l0r, l1r, l2r, l3r;
                    LDSM4T(h0r, h1r, h2r, h3r, ab);
                    LDSM4T(l0r, l1r, l2r, l3r, ab + 16384u);
                    MMA(acc1[2 * g],      AH0, AH1, AH2, AH3, h0r, h1r);
                    MMA(acc1[2 * g + 1],  AH0, AH1, AH2, AH3, h2r, h3r);
                    MMA(acc2a[2 * g],     AH0, AH1, AH2, AH3, l0r, l1r);
                    MMA(acc2a[2 * g + 1], AH0, AH1, AH2, AH3, l2r, l3r);
                    MMA(acc2b[2 * g],     AL0, AL1, AL2, AL3, h0r, h1r);
                    MMA(acc2b[2 * g + 1], AL0, AL1, AL2, AL3, h2r, h3r);
                }
            }

            // -------- phase 4: epilogue (packed conversions, conflict-free half2 stores) --------
#pragma unroll
            for (int nt = 0; nt < 8; nt++) {
                const uint32_t ntoff = 16u * nt;
                float h00 = fast_tanh(fmaf(acc2a[nt][0] + acc2b[nt][0], INV_LO, acc1[nt][0]));
                float h01 = fast_tanh(fmaf(acc2a[nt][1] + acc2b[nt][1], INV_LO, acc1[nt][1]));
                float h10 = fast_tanh(fmaf(acc2a[nt][2] + acc2b[nt][2], INV_LO, acc1[nt][2]));
                float h11 = fast_tanh(fmaf(acc2a[nt][3] + acc2b[nt][3], INV_LO, acc1[nt][3]));
                __half2 H0 = __floats2half2_rn(h00, h01);
                __half2 H1 = __floats2half2_rn(h10, h11);
                float2 f0 = __half22float2(H0), f1 = __half22float2(H1);
                __half2 L0 = __floats2half2_rn((h00 - f0.x) * SCALE_LO, (h01 - f0.y) * SCALE_LO);
                __half2 L1 = __floats2half2_rn((h10 - f1.x) * SCALE_LO, (h11 - f1.y) * SCALE_LO);
                *(__half2*)(sm + S_BH_HI + oj0 + ntoff) = H0;
                *(__half2*)(sm + S_BH_LO + oj0 + ntoff) = L0;
                *(__half2*)(sm + S_BH_HI + oj1 + ntoff) = H1;
                *(__half2*)(sm + S_BH_LO + oj1 + ntoff) = L1;
                if (last) {
                    float p0 = h00 * w0 + h10 * w1;
                    float p1 = h01 * w0 + h11 * w1;
#pragma unroll
                    for (int d = 4; d < 32; d <<= 1) {
                        p0 += __shfl_xor_sync(0xFFFFFFFFu, p0, d);
                        p1 += __shfl_xor_sync(0xFFFFFFFFu, p1, d);
                    }
                    if (lane < 4) {
                        sRed[wm * 64 + nt * 8 + 2 * (lane & 3)]     = p0;
                        sRed[wm * 64 + nt * 8 + 2 * (lane & 3) + 1] = p1;
                    }
                }
            }
        }
        // backpressure poll before copy-out
        if (!last && t >= RING_D)
            while (ld_acq(&g_cons[pc_out]) < (unsigned)(t + 1 - RING_D)) {}
        __syncthreads();   // BH (and sRed) writes complete

        if (!last) {
            float4* dst = (float4*)(ring_out + (size_t)(t & (RING_D - 1)) * RING_SLOT);
            const float4* src = (const float4*)(sm + S_BH_HI);
#pragma unroll
            for (int i = 0; i < 8; i++) dst[tid + i * NTHREADS] = src[tid + i * NTHREADS];
            __syncthreads();
            if (tid == 0) st_rel(&g_prod[pc_out], (unsigned)(t + 1));
        } else {
            if (tid < CHUNKB) {
                float s = boutv;
#pragma unroll
                for (int w = 0; w < 7; w++) s += sRed[w * 64 + tid];
                out[(size_t)(b0 + tid) * TSTEPS + t] = s;
            }
            __syncthreads();
        }
    }

    // ---- final hidden state ----
    for (int idx = tid; idx < CHUNKB * HID; idx += NTHREADS) {
        int b = idx & 63, jj = idx >> 6;
        uint32_t o = b_off(jj, b);
        float v = __half2float(*(const __half*)(sm + S_BH_HI + o))
                + __half2float(*(const __half*)(sm + S_BH_LO + o)) * INV_LO;
        out[(size_t)BATCH * TSTEPS + ((size_t)l * BATCH + b0 + b) * HID + jj] = v;
    }
}

extern "C" void kernel_launch(void* const* d_in, const int* in_sizes, int n_in,
                              void* d_out, int out_size) {
    const float* x    = (const float*)d_in[0];
    const float* h0   = (const float*)d_in[1];
    const float* Wi0  = (const float*)d_in[2];
    const float* Wih  = (const float*)d_in[3];
    const float* Whh  = (const float*)d_in[4];
    const float* bih  = (const float*)d_in[5];
    const float* bhh  = (const float*)d_in[6];
    const float* Wout = (const float*)d_in[7];
    const float* bout = (const float*)d_in[8];
    float* out = (float*)d_out;

    cudaFuncSetAttribute(rnn_mma_kernel, cudaFuncAttributeMaxDynamicSharedMemorySize, SMEM_BYTES);
    rnn_reset_kernel<<<1, 256>>>();
    rnn_mma_kernel<<<NSTAGES * NCHUNK, NTHREADS, SMEM_BYTES>>>(
        x, h0, Wi0, Wih, Whh, bih, bhh, Wout, bout, out);
}

// round 12
// speedup vs baseline: 1.4434x; 1.1069x over previous
#include <cuda_runtime.h>
#include <cuda_fp16.h>
#include <cstdint>

#define HID      100
#define BATCH    512
#define TSTEPS   512
#define NCHUNK   8
#define CHUNKB   64
#define NSTAGES  10
#define NTHREADS 352
#define NCOMM_T  128                     // comms threads (warps 7..10)
#define RING_D   4
#define NPAIRS   ((NSTAGES-1)*NCHUNK)   // 72

#define SCALE_LO 2048.0f
#define INV_LO   (1.0f/2048.0f)
#define APITCH   464     // A row pitch (bytes): conflict-free ldmatrix phases
#define BPITCH   144     // B row pitch (bytes): [k][n] f16

// ---- smem byte offsets ----
#define S_RED    0                        // 2048
#define S_BI_HI  2048                     // B input region  [112 k][64 n] f16 (16KB slot)
#define S_BI_LO  (S_BI_HI + 16384)
#define S_BH_HI  (S_BI_LO + 16384)        // B hidden region
#define S_BH_LO  (S_BH_HI + 16384)
#define S_A_HI   (S_BH_LO + 16384)        // A [128 m][224 k] f16, pitch 464B
#define S_A_LO   (S_A_HI + 128*APITCH)
#define SMEM_BYTES (S_A_LO + 128*APITCH)  // 186368

#define RING_SLOT 32768
__device__ unsigned char g_ring[(size_t)NPAIRS * RING_D * RING_SLOT];
__device__ unsigned g_prod[NPAIRS];
__device__ unsigned g_cons[NPAIRS];

#define BAR_SYNC(id, cnt)   asm volatile("bar.sync %0, %1;"   :: "n"(id), "n"(cnt) : "memory")
#define BAR_ARRIVE(id, cnt) asm volatile("bar.arrive %0, %1;" :: "n"(id), "n"(cnt) : "memory")

__device__ __forceinline__ uint32_t smem_u32(const void* p) {
    uint32_t a;
    asm("{ .reg .u64 t; cvta.to.shared.u64 t, %1; cvt.u32.u64 %0, t; }" : "=r"(a) : "l"(p));
    return a;
}
__device__ __forceinline__ unsigned ld_acq(const unsigned* p) {
    unsigned v;
    asm volatile("ld.acquire.gpu.global.u32 %0, [%1];" : "=r"(v) : "l"(p) : "memory");
    return v;
}
__device__ __forceinline__ void st_rel(unsigned* p, unsigned v) {
    asm volatile("st.release.gpu.global.u32 [%0], %1;" :: "l"(p), "r"(v) : "memory");
}

#define LDSM4(r0, r1, r2, r3, addr) \
    asm volatile("ldmatrix.sync.aligned.m8n8.x4.shared.b16 {%0,%1,%2,%3}, [%4];" \
        : "=r"(r0), "=r"(r1), "=r"(r2), "=r"(r3) : "r"(addr))
#define LDSM4T(r0, r1, r2, r3, addr) \
    asm volatile("ldmatrix.sync.aligned.m8n8.x4.trans.shared.b16 {%0,%1,%2,%3}, [%4];" \
        : "=r"(r0), "=r"(r1), "=r"(r2), "=r"(r3) : "r"(addr))

#define MMA(d, a0_, a1_, a2_, a3_, b0_, b1_) \
    asm volatile("mma.sync.aligned.m16n8k16.row.col.f32.f16.f16.f32 " \
        "{%0,%1,%2,%3}, {%4,%5,%6,%7}, {%8,%9}, {%0,%1,%2,%3};" \
        : "+f"((d)[0]), "+f"((d)[1]), "+f"((d)[2]), "+f"((d)[3]) \
        : "r"(a0_), "r"(a1_), "r"(a2_), "r"(a3_), "r"(b0_), "r"(b1_))

__device__ __forceinline__ void split16(float v, __half& hi, __half& lo) {
    hi = __float2half_rn(v);
    lo = __float2half_rn((v - __half2float(hi)) * SCALE_LO);
}
__device__ __forceinline__ float fast_tanh(float x) {
    float e, r;
    asm("ex2.approx.f32 %0, %1;" : "=f"(e) : "f"(x * 2.8853900817779268f)); // 2*log2(e)
    asm("rcp.approx.f32 %0, %1;" : "=f"(r) : "f"(e + 1.0f));
    return fmaf(-2.0f, r, 1.0f);
}
__device__ __forceinline__ uint32_t b_off(int k, int n) {
    return (uint32_t)k * BPITCH + 2u * (uint32_t)n;
}

__global__ void rnn_reset_kernel() {
    int i = threadIdx.x;
    if (i < NPAIRS) { g_prod[i] = 0u; g_cons[i] = 0u; }
}

__global__ __launch_bounds__(NTHREADS, 1)
void rnn_mma_kernel(const float* __restrict__ x,    const float* __restrict__ h0,
                    const float* __restrict__ Wi0,  const float* __restrict__ Wih,
                    const float* __restrict__ Whh,  const float* __restrict__ bih,
                    const float* __restrict__ bhh,  const float* __restrict__ Wout,
                    const float* __restrict__ bout, float* __restrict__ out)
{
    extern __shared__ __align__(128) unsigned char sm[];
    const uint32_t smb = smem_u32(sm);
    const int tid = threadIdx.x, warp = tid >> 5, lane = tid & 31;
    const int stage = blockIdx.x >> 3, chunk = blockIdx.x & 7;
    const int b0 = chunk * CHUNKB, l = stage;
    const bool first = (stage == 0), last = (stage == NSTAGES - 1);
    const bool mwarp = (warp < 7);
    const int ct = tid - 224;                // comms thread index [0,128) when warp>=7

    // ---- zero all smem ----
    for (int i = tid; i < SMEM_BYTES / 16; i += NTHREADS)
        ((float4*)sm)[i] = make_float4(0.f, 0.f, 0.f, 0.f);
    __syncthreads();

    // ---- A fill: [m 128][k 224] f16, pitch 464B. I=k[0,112), H=k[112,224) ----
    if (first) {
        for (int idx = tid; idx < HID * HID; idx += NTHREADS) {
            int jj = idx / HID, kk = idx % HID;
            __half hi, lo; split16(Whh[idx], hi, lo);
            uint32_t o = (uint32_t)jj * APITCH + 2u * (112 + kk);
            *(__half*)(sm + S_A_HI + o) = hi; *(__half*)(sm + S_A_LO + o) = lo;
        }
        for (int jj = tid; jj < HID; jj += NTHREADS) {
            __half hi, lo; split16(Wi0[jj], hi, lo);
            uint32_t o = (uint32_t)jj * APITCH;              // x weight at k=0
            *(__half*)(sm + S_A_HI + o) = hi; *(__half*)(sm + S_A_LO + o) = lo;
        }
    } else {
        for (int idx = tid; idx < 2 * HID * HID; idx += NTHREADS) {
            int m = idx / (HID * HID), r = idx % (HID * HID);
            int jj = r / HID, kk = r % HID;
            float v = m ? Whh[(size_t)l * HID * HID + r] : Wih[(size_t)(l - 1) * HID * HID + r];
            __half hi, lo; split16(v, hi, lo);
            uint32_t o = (uint32_t)jj * APITCH + 2u * (m ? 112 + kk : kk);
            *(__half*)(sm + S_A_HI + o) = hi; *(__half*)(sm + S_A_LO + o) = lo;
        }
    }
    // ---- BH fill from h0: row k=jj, col n=b ----
    for (int idx = tid; idx < CHUNKB * HID; idx += NTHREADS) {
        int b = idx & 63, jj = idx >> 6;
        __half hi, lo; split16(h0[((size_t)l * BATCH + b0 + b) * HID + jj], hi, lo);
        uint32_t o = b_off(jj, b);
        *(__half*)(sm + S_BH_HI + o) = hi;
        *(__half*)(sm + S_BH_LO + o) = lo;
    }
    __syncthreads();

    const int pc_in = (stage - 1) * NCHUNK + chunk, pc_out = stage * NCHUNK + chunk;
    unsigned char* ring_in  = g_ring + (size_t)pc_in  * RING_D * RING_SLOT;
    unsigned char* ring_out = g_ring + (size_t)pc_out * RING_D * RING_SLOT;
    float* sRed = (float*)(sm + S_RED);
    const float boutv = bout[0];

    if (mwarp) {
        // ================= MMA warps 0..6 =================
        const int wm = warp;
        const uint32_t aRow = 16u * (uint32_t)wm + (uint32_t)(lane & 15);
        const uint32_t aCol = ((uint32_t)(lane >> 4)) << 4;
        const uint32_t aHiBase = smb + S_A_HI + aRow * APITCH + aCol;
        const uint32_t aLoBase = smb + S_A_LO + aRow * APITCH + aCol;
        const uint32_t brp = ((uint32_t)((lane & 7) + ((lane >> 3) & 1) * 8)) * BPITCH
                           + 16u * (uint32_t)(lane >> 4);
        const int j0 = 16 * wm + (lane >> 2), j1 = j0 + 8;
        float bias0 = 0.f, bias1 = 0.f, w0 = 0.f, w1 = 0.f;
        if (j0 < HID) bias0 = bih[l * HID + j0] + bhh[l * HID + j0];
        if (j1 < HID) bias1 = bih[l * HID + j1] + bhh[l * HID + j1];
        if (last) {
            if (j0 < HID) w0 = Wout[j0];
            if (j1 < HID) w1 = Wout[j1];
        }
        const uint32_t tcol = 4u * (uint32_t)(lane & 3);
        const uint32_t oj0 = (uint32_t)j0 * BPITCH + tcol;
        const uint32_t oj1 = (uint32_t)j1 * BPITCH + tcol;

        for (int t = 0; t < TSTEPS; t++) {
            // ---- phase 1: hidden-part MMA ----
            float acc1[8][4], acc2a[8][4], acc2b[8][4];
#pragma unroll
            for (int nt = 0; nt < 8; nt++) {
                acc1[nt][0] = bias0; acc1[nt][1] = bias0;
                acc1[nt][2] = bias1; acc1[nt][3] = bias1;
#pragma unroll
                for (int r = 0; r < 4; r++) { acc2a[nt][r] = 0.f; acc2b[nt][r] = 0.f; }
            }
#pragma unroll
            for (int ci = 0; ci < 7; ci++) {
                uint32_t AH0, AH1, AH2, AH3, AL0, AL1, AL2, AL3;
                LDSM4(AH0, AH1, AH2, AH3, aHiBase + 32u * (ci + 7));
                LDSM4(AL0, AL1, AL2, AL3, aLoBase + 32u * (ci + 7));
                uint32_t bb = smb + S_BH_HI + (uint32_t)ci * (16u * BPITCH) + brp;
#pragma unroll
                for (int g = 0; g < 4; g++) {
                    uint32_t ab = bb + 32u * g;
                    uint32_t h0r, h1r, h2r, h3r, l0r, l1r, l2r, l3r;
                    LDSM4T(h0r, h1r, h2r, h3r, ab);
                    LDSM4T(l0r, l1r, l2r, l3r, ab + 16384u);
                    MMA(acc1[2 * g],      AH0, AH1, AH2, AH3, h0r, h1r);
                    MMA(acc1[2 * g + 1],  AH0, AH1, AH2, AH3, h2r, h3r);
                    MMA(acc2a[2 * g],     AH0, AH1, AH2, AH3, l0r, l1r);
                    MMA(acc2a[2 * g + 1], AH0, AH1, AH2, AH3, l2r, l3r);
                    MMA(acc2b[2 * g],     AL0, AL1, AL2, AL3, h0r, h1r);
                    MMA(acc2b[2 * g + 1], AL0, AL1, AL2, AL3, h2r, h3r);
                }
            }

            BAR_SYNC(1, NTHREADS);   // input t staged by comms

            // ---- phase 3: input-part MMA ----
#pragma unroll
            for (int ci = 0; ci < 7; ci++) {
                if (first && ci >= 1) break;
                uint32_t AH0, AH1, AH2, AH3, AL0, AL1, AL2, AL3;
                LDSM4(AH0, AH1, AH2, AH3, aHiBase + 32u * ci);
                LDSM4(AL0, AL1, AL2, AL3, aLoBase + 32u * ci);
                uint32_t bb = smb + S_BI_HI + (uint32_t)ci * (16u * BPITCH) + brp;
#pragma unroll
                for (int g = 0; g < 4; g++) {
                    uint32_t ab = bb + 32u * g;
                    uint32_t h0r, h1r, h2r, h3r, l0r, l1r, l2r, l3r;
                    LDSM4T(h0r, h1r, h2r, h3r, ab);
                    LDSM4T(l0r, l1r, l2r, l3r, ab + 16384u);
                    MMA(acc1[2 * g],      AH0, AH1, AH2, AH3, h0r, h1r);
                    MMA(acc1[2 * g + 1],  AH0, AH1, AH2, AH3, h2r, h3r);
                    MMA(acc2a[2 * g],     AH0, AH1, AH2, AH3, l0r, l1r);
                    MMA(acc2a[2 * g + 1], AH0, AH1, AH2, AH3, l2r, l3r);
                    MMA(acc2b[2 * g],     AL0, AL1, AL2, AL3, h0r, h1r);
                    MMA(acc2b[2 * g + 1], AL0, AL1, AL2, AL3, h2r, h3r);
                }
            }

            BAR_SYNC(3, NTHREADS);   // comms done copying BH(t-1) / out(t-1): safe to overwrite

            // ---- epilogue ----
#pragma unroll
            for (int nt = 0; nt < 8; nt++) {
                const uint32_t ntoff = 16u * nt;
                float h00 = fast_tanh(fmaf(acc2a[nt][0] + acc2b[nt][0], INV_LO, acc1[nt][0]));
                float h01 = fast_tanh(fmaf(acc2a[nt][1] + acc2b[nt][1], INV_LO, acc1[nt][1]));
                float h10 = fast_tanh(fmaf(acc2a[nt][2] + acc2b[nt][2], INV_LO, acc1[nt][2]));
                float h11 = fast_tanh(fmaf(acc2a[nt][3] + acc2b[nt][3], INV_LO, acc1[nt][3]));
                __half2 H0 = __floats2half2_rn(h00, h01);
                __half2 H1 = __floats2half2_rn(h10, h11);
                float2 f0 = __half22float2(H0), f1 = __half22float2(H1);
                __half2 L0 = __floats2half2_rn((h00 - f0.x) * SCALE_LO, (h01 - f0.y) * SCALE_LO);
                __half2 L1 = __floats2half2_rn((h10 - f1.x) * SCALE_LO, (h11 - f1.y) * SCALE_LO);
                *(__half2*)(sm + S_BH_HI + oj0 + ntoff) = H0;
                *(__half2*)(sm + S_BH_LO + oj0 + ntoff) = L0;
                *(__half2*)(sm + S_BH_HI + oj1 + ntoff) = H1;
                *(__half2*)(sm + S_BH_LO + oj1 + ntoff) = L1;
                if (last) {
                    float p0 = h00 * w0 + h10 * w1;
                    float p1 = h01 * w0 + h11 * w1;
#pragma unroll
                    for (int d = 4; d < 32; d <<= 1) {
                        p0 += __shfl_xor_sync(0xFFFFFFFFu, p0, d);
                        p1 += __shfl_xor_sync(0xFFFFFFFFu, p1, d);
                    }
                    if (lane < 4) {
                        sRed[wm * 64 + nt * 8 + 2 * (lane & 3)]     = p0;
                        sRed[wm * 64 + nt * 8 + 2 * (lane & 3) + 1] = p1;
                    }
                }
            }

            BAR_SYNC(2, NTHREADS);   // BH(t)/sRed visible to everyone
        }
    } else {
        // ================= comms warps 7..10 (128 threads) =================
        float xv = 0.f;
        if (first && ct < CHUNKB) xv = x[(size_t)(b0 + ct) * TSTEPS];
        BAR_ARRIVE(3, NTHREADS);     // pre-seed bar3 for t=0

        for (int t = 0; t < TSTEPS; t++) {
            // ---- stage input t into BI ----
            if (first) {
                if (ct < CHUNKB) {
                    __half hi, lo; split16(xv, hi, lo);
                    *(__half*)(sm + S_BI_HI + 2u * ct) = hi;   // row k=0
                    *(__half*)(sm + S_BI_LO + 2u * ct) = lo;
                    if (t + 1 < TSTEPS) xv = x[(size_t)(b0 + ct) * TSTEPS + t + 1];
                }
            } else {
                while (ld_acq(&g_prod[pc_in]) < (unsigned)(t + 1)) {}
                const float4* src = (const float4*)(ring_in + (size_t)(t & (RING_D - 1)) * RING_SLOT);
                float4 pf[16];
#pragma unroll
                for (int i = 0; i < 16; i++) pf[i] = __ldcg(src + ct + i * NCOMM_T);
                float4* dst = (float4*)(sm + S_BI_HI);
#pragma unroll
                for (int i = 0; i < 16; i++) dst[ct + i * NCOMM_T] = pf[i];
            }
            BAR_ARRIVE(1, NTHREADS);     // input t ready

            BAR_SYNC(2, NTHREADS);       // epilogue t done: BH(t)/sRed valid
            if (!first && ct == 0) st_rel(&g_cons[pc_in], (unsigned)(t + 1));

            if (!last) {
                if (t >= RING_D)
                    while (ld_acq(&g_cons[pc_out]) < (unsigned)(t + 1 - RING_D)) {}
                float4* dst = (float4*)(ring_out + (size_t)(t & (RING_D - 1)) * RING_SLOT);
                const float4* src = (const float4*)(sm + S_BH_HI);
#pragma unroll
                for (int i = 0; i < 16; i++) dst[ct + i * NCOMM_T] = src[ct + i * NCOMM_T];
                BAR_SYNC(4, NCOMM_T);    // drain comms stores
                if (ct == 0) st_rel(&g_prod[pc_out], (unsigned)(t + 1));
            } else {
                if (ct < CHUNKB) {
                    float s = boutv;
#pragma unroll
                    for (int w = 0; w < 7; w++) s += sRed[w * 64 + ct];
                    out[(size_t)(b0 + ct) * TSTEPS + t] = s;
                }
            }
            BAR_ARRIVE(3, NTHREADS);     // copy/out of step t done
        }
    }

    // ---- final hidden state ----
    __syncthreads();
    for (int idx = tid; idx < CHUNKB * HID; idx += NTHREADS) {
        int b = idx & 63, jj = idx >> 6;
        uint32_t o = b_off(jj, b);
        float v = __half2float(*(const __half*)(sm + S_BH_HI + o))
                + __half2float(*(const __half*)(sm + S_BH_LO + o)) * INV_LO;
        out[(size_t)BATCH * TSTEPS + ((size_t)l * BATCH + b0 + b) * HID + jj] = v;
    }
}

extern "C" void kernel_launch(void* const* d_in, const int* in_sizes, int n_in,
                              void* d_out, int out_size) {
    const float* x    = (const float*)d_in[0];
    const float* h0   = (const float*)d_in[1];
    const float* Wi0  = (const float*)d_in[2];
    const float* Wih  = (const float*)d_in[3];
    const float* Whh  = (const float*)d_in[4];
    const float* bih  = (const float*)d_in[5];
    const float* bhh  = (const float*)d_in[6];
    const float* Wout = (const float*)d_in[7];
    const float* bout = (const float*)d_in[8];
    float* out = (float*)d_out;

    cudaFuncSetAttribute(rnn_mma_kernel, cudaFuncAttributeMaxDynamicSharedMemorySize, SMEM_BYTES);
    rnn_reset_kernel<<<1, 256>>>();
    rnn_mma_kernel<<<NSTAGES * NCHUNK, NTHREADS, SMEM_BYTES>>>(
        x, h0, Wi0, Wih, Whh, bih, bhh, Wout, bout, out);
}